// round 3
// baseline (speedup 1.0000x reference)
#include <cuda_runtime.h>

#define RNN_B 128
#define RNN_T 64
#define RNN_D 256
#define RNN_H 256

// 64 persistent CTAs, each owns 2 batch rows and runs the full T=64 x 2-layer
// recurrence independently (the cell graph has no cross-batch coupling).
// 256 threads: thread j computes output column j for both rows at every stage.
// All CTAs stream the same weights in near-lockstep -> DRAM sees the weights
// once; L2 absorbs the 64x replication.

__device__ __forceinline__ void cell2(
    float (&xs)[2][RNN_H],              // stage-0 input rows (smem)
    float (&hs)[2][RNN_H],              // hidden rows (smem); overwritten with h_new
    const float* __restrict__ Wi,       // [D,H] for this timestep
    const float* __restrict__ Wh,       // [3,H,H] for this timestep
    const float* __restrict__ bias,     // [3,H] for this timestep
    float (&n0s)[2][RNN_H],
    float (&n1s)[2][RNN_H],
    int j)
{
    constexpr int H = RNN_H;

    // ---------- node 0: tanh(x@Wi + h@Wh[0] + b[0]) ----------
    float ax0 = 0.f, ah0 = 0.f, ax1 = 0.f, ah1 = 0.f;
    {
        const float4* xv0 = reinterpret_cast<const float4*>(xs[0]);
        const float4* xv1 = reinterpret_cast<const float4*>(xs[1]);
        const float4* hv0 = reinterpret_cast<const float4*>(hs[0]);
        const float4* hv1 = reinterpret_cast<const float4*>(hs[1]);
        const float* wi = Wi + j;
        const float* wh = Wh + j;
        #pragma unroll 8
        for (int q = 0; q < H / 4; ++q) {
            float4 X0 = xv0[q], X1 = xv1[q];
            float4 Hh0 = hv0[q], Hh1 = hv1[q];
            float w0 = wi[0 * H], w1 = wi[1 * H], w2 = wi[2 * H], w3 = wi[3 * H];
            float u0 = wh[0 * H], u1 = wh[1 * H], u2 = wh[2 * H], u3 = wh[3 * H];
            ax0 = fmaf(X0.x, w0, fmaf(X0.y, w1, fmaf(X0.z, w2, fmaf(X0.w, w3, ax0))));
            ah0 = fmaf(Hh0.x, u0, fmaf(Hh0.y, u1, fmaf(Hh0.z, u2, fmaf(Hh0.w, u3, ah0))));
            ax1 = fmaf(X1.x, w0, fmaf(X1.y, w1, fmaf(X1.z, w2, fmaf(X1.w, w3, ax1))));
            ah1 = fmaf(Hh1.x, u0, fmaf(Hh1.y, u1, fmaf(Hh1.z, u2, fmaf(Hh1.w, u3, ah1))));
            wi += 4 * H;
            wh += 4 * H;
        }
    }
    float b0j = bias[j];
    float v0 = tanhf(ax0 + ah0 + b0j);
    float v1 = tanhf(ax1 + ah1 + b0j);
    n0s[0][j] = v0;
    n0s[1][j] = v1;
    __syncthreads();

    // ---------- node 1: relu(n0@Wh[1] + b[1]) + n0 ----------
    float p0 = 0.f, r0a = 0.f, p1 = 0.f, r1a = 0.f;
    {
        const float4* a0 = reinterpret_cast<const float4*>(n0s[0]);
        const float4* a1 = reinterpret_cast<const float4*>(n0s[1]);
        const float* w = Wh + (size_t)H * H + j;
        #pragma unroll 8
        for (int q = 0; q < H / 4; ++q) {
            float4 A0 = a0[q], A1 = a1[q];
            float w0 = w[0 * H], w1 = w[1 * H], w2 = w[2 * H], w3 = w[3 * H];
            p0  = fmaf(A0.x, w0, fmaf(A0.y, w1, p0));
            r0a = fmaf(A0.z, w2, fmaf(A0.w, w3, r0a));
            p1  = fmaf(A1.x, w0, fmaf(A1.y, w1, p1));
            r1a = fmaf(A1.z, w2, fmaf(A1.w, w3, r1a));
            w += 4 * H;
        }
    }
    float b1j = bias[H + j];
    float u0 = fmaxf(p0 + r0a + b1j, 0.f) + v0;
    float u1 = fmaxf(p1 + r1a + b1j, 0.f) + v1;
    n1s[0][j] = u0;
    n1s[1][j] = u1;
    __syncthreads();

    // ---------- node 2: sigmoid(n1@Wh[2] + b[2]) + n0 ; h_new = 0.5*(n1+n2) ----------
    float s0 = 0.f, s0b = 0.f, s1 = 0.f, s1b = 0.f;
    {
        const float4* a0 = reinterpret_cast<const float4*>(n1s[0]);
        const float4* a1 = reinterpret_cast<const float4*>(n1s[1]);
        const float* w = Wh + 2 * (size_t)H * H + j;
        #pragma unroll 8
        for (int q = 0; q < H / 4; ++q) {
            float4 A0 = a0[q], A1 = a1[q];
            float w0 = w[0 * H], w1 = w[1 * H], w2 = w[2 * H], w3 = w[3 * H];
            s0  = fmaf(A0.x, w0, fmaf(A0.y, w1, s0));
            s0b = fmaf(A0.z, w2, fmaf(A0.w, w3, s0b));
            s1  = fmaf(A1.x, w0, fmaf(A1.y, w1, s1));
            s1b = fmaf(A1.z, w2, fmaf(A1.w, w3, s1b));
            w += 4 * H;
        }
    }
    float b2j = bias[2 * H + j];
    float g0 = 1.f / (1.f + expf(-(s0 + s0b + b2j))) + v0;
    float g1 = 1.f / (1.f + expf(-(s1 + s1b + b2j))) + v1;

    // hs last read in node-0 stage (two syncs ago) -> safe to overwrite
    hs[0][j] = 0.5f * (u0 + g0);
    hs[1][j] = 0.5f * (u1 + g1);
    __syncthreads();   // publish h_new before anyone reads it
}

__global__ void __launch_bounds__(256, 1)
rnn_persist_kernel(const float* __restrict__ x,       // [B,T,D]
                   const float* __restrict__ hidden,  // [L,B,H]
                   const float* __restrict__ Win0,    // [T,D,H]
                   const float* __restrict__ Wh0,     // [T,3,H,H]
                   const float* __restrict__ b0,      // [T,3,H]
                   const float* __restrict__ Win1,    // [T,H,H]
                   const float* __restrict__ Wh1,     // [T,3,H,H]
                   const float* __restrict__ b1,      // [T,3,H]
                   float* __restrict__ out,           // [B,T,H]
                   float* __restrict__ hout)          // [L,B,H]
{
    constexpr int H = RNN_H;
    __shared__ float xs[2][H];
    __shared__ float h0s[2][H];
    __shared__ float h1s[2][H];
    __shared__ float n0s[2][H];
    __shared__ float n1s[2][H];

    const int j = threadIdx.x;
    const int r0 = blockIdx.x * 2;
    const int r1 = r0 + 1;

    h0s[0][j] = hidden[r0 * H + j];
    h0s[1][j] = hidden[r1 * H + j];
    h1s[0][j] = hidden[RNN_B * H + r0 * H + j];
    h1s[1][j] = hidden[RNN_B * H + r1 * H + j];
    __syncthreads();

    for (int t = 0; t < RNN_T; ++t) {
        // layer-0 input rows for this timestep
        xs[0][j] = x[(r0 * RNN_T + t) * RNN_D + j];
        xs[1][j] = x[(r1 * RNN_T + t) * RNN_D + j];
        __syncthreads();

        // layer 0 cell (updates h0s in place; h0s is layer-1's input)
        cell2(xs, h0s,
              Win0 + (size_t)t * RNN_D * H,
              Wh0 + (size_t)t * 3 * H * H,
              b0 + (size_t)t * 3 * H,
              n0s, n1s, j);

        // layer 1 cell (input = fresh h0s, updates h1s in place)
        cell2(h0s, h1s,
              Win1 + (size_t)t * H * H,
              Wh1 + (size_t)t * 3 * H * H,
              b1 + (size_t)t * 3 * H,
              n0s, n1s, j);

        // h1s[b][j] was written by this very thread — no sync needed
        out[(r0 * RNN_T + t) * H + j] = h1s[0][j];
        out[(r1 * RNN_T + t) * H + j] = h1s[1][j];
    }

    hout[r0 * H + j] = h0s[0][j];
    hout[r1 * H + j] = h0s[1][j];
    hout[RNN_B * H + r0 * H + j] = h1s[0][j];
    hout[RNN_B * H + r1 * H + j] = h1s[1][j];
}

extern "C" void kernel_launch(void* const* d_in, const int* in_sizes, int n_in,
                              void* d_out, int out_size) {
    const float* x      = (const float*)d_in[0];
    const float* hidden = (const float*)d_in[1];
    const float* Win0   = (const float*)d_in[2];
    const float* Wh0    = (const float*)d_in[3];
    const float* b0     = (const float*)d_in[4];
    const float* Win1   = (const float*)d_in[5];
    const float* Wh1    = (const float*)d_in[6];
    const float* b1     = (const float*)d_in[7];

    float* out  = (float*)d_out;                          // [B,T,H]
    float* hout = out + (size_t)RNN_B * RNN_T * RNN_H;    // [L,B,H]

    rnn_persist_kernel<<<RNN_B / 2, 256>>>(x, hidden, Win0, Wh0, b0,
                                           Win1, Wh1, b1, out, hout);
}

// round 4
// speedup vs baseline: 2.4037x; 2.4037x over previous
#include <cuda_runtime.h>

#define B_ 128
#define T_ 64
#define D_ 256
#define H_ 256
#define NT 512

// 64 persistent CTAs x 512 threads. Each CTA owns 2 batch rows and runs the
// whole T=64 x 2-layer recurrence with no inter-CTA sync (batch rows are
// independent in this cell graph). Per GEMM stage: thread (q, kc) with
// q = tid&63 (4 output columns 4q..4q+3), kc = tid>>6 (k-chunk of 32)
// computes a float4 partial for both batch rows with LDG.128 weight loads;
// 128 reducer threads fold the 8 partials, apply bias+activation, and
// publish to smem.

__device__ __forceinline__ void f4fma(float4& a, float s, const float4 w) {
    a.x = fmaf(s, w.x, a.x); a.y = fmaf(s, w.y, a.y);
    a.z = fmaf(s, w.z, a.z); a.w = fmaf(s, w.w, a.w);
}
__device__ __forceinline__ float4 f4add(float4 a, float4 b) {
    return make_float4(a.x + b.x, a.y + b.y, a.z + b.z, a.w + b.w);
}

// Partial mat-vec for both rows: acc += a[rows][kc*32 .. kc*32+31] @ W[k, 4q..4q+3]
__device__ __forceinline__ void mv_partial(
    const float* __restrict__ W,          // [256,256] row-major
    const float* __restrict__ a0,         // smem row 0 [256]
    const float* __restrict__ a1,         // smem row 1 [256]
    float4& acc0, float4& acc1, int q, int kc)
{
    const float4* __restrict__ w4 =
        reinterpret_cast<const float4*>(W) + (size_t)(kc * 32) * (H_ / 4) + q;
    const float4* __restrict__ av0 = reinterpret_cast<const float4*>(a0) + kc * 8;
    const float4* __restrict__ av1 = reinterpret_cast<const float4*>(a1) + kc * 8;
    #pragma unroll
    for (int g = 0; g < 4; ++g) {
        float4 w[8];
        #pragma unroll
        for (int k = 0; k < 8; ++k) w[k] = w4[(g * 8 + k) * (H_ / 4)];
        float4 A0a = av0[g * 2], A0b = av0[g * 2 + 1];
        float4 A1a = av1[g * 2], A1b = av1[g * 2 + 1];
        f4fma(acc0, A0a.x, w[0]); f4fma(acc1, A1a.x, w[0]);
        f4fma(acc0, A0a.y, w[1]); f4fma(acc1, A1a.y, w[1]);
        f4fma(acc0, A0a.z, w[2]); f4fma(acc1, A1a.z, w[2]);
        f4fma(acc0, A0a.w, w[3]); f4fma(acc1, A1a.w, w[3]);
        f4fma(acc0, A0b.x, w[4]); f4fma(acc1, A1b.x, w[4]);
        f4fma(acc0, A0b.y, w[5]); f4fma(acc1, A1b.y, w[5]);
        f4fma(acc0, A0b.z, w[6]); f4fma(acc1, A1b.z, w[6]);
        f4fma(acc0, A0b.w, w[7]); f4fma(acc1, A1b.w, w[7]);
    }
}

__device__ __forceinline__ float4 reduce8(const float4 (&part)[8][2][64],
                                          int row, int q) {
    float4 s = f4add(part[0][row][q], part[1][row][q]);
    float4 s2 = f4add(part[2][row][q], part[3][row][q]);
    float4 s3 = f4add(part[4][row][q], part[5][row][q]);
    float4 s4 = f4add(part[6][row][q], part[7][row][q]);
    return f4add(f4add(s, s2), f4add(s3, s4));
}

__device__ __forceinline__ void cell(
    const float (&in)[2][H_],             // stage-0 "x" input rows (smem)
    float (&h)[2][H_],                    // hidden rows (smem); overwritten
    float (&n0s)[2][H_], float (&n1s)[2][H_],
    float4 (&part)[8][2][64],
    const float* __restrict__ Wi,         // [256,256]
    const float* __restrict__ Wh,         // [3,256,256]
    const float* __restrict__ bias,       // [3,256]
    int tid, int q, int kc,
    float* __restrict__ o0, float* __restrict__ o1)  // gmem out rows or null
{
    // ---------- node 0: tanh(x@Wi + h@Wh[0] + b[0]) ----------
    {
        float4 a0 = {0.f, 0.f, 0.f, 0.f}, a1 = {0.f, 0.f, 0.f, 0.f};
        mv_partial(Wi, in[0], in[1], a0, a1, q, kc);
        mv_partial(Wh, h[0], h[1], a0, a1, q, kc);
        part[kc][0][q] = a0;
        part[kc][1][q] = a1;
    }
    __syncthreads();

    float4 v0 = {0.f, 0.f, 0.f, 0.f};    // reducer-persistent n0
    float4 u  = {0.f, 0.f, 0.f, 0.f};    // reducer-persistent n1
    if (tid < 128) {
        const int row = tid >> 6;
        float4 s = reduce8(part, row, q);
        float4 bv = *reinterpret_cast<const float4*>(bias + 4 * q);
        v0.x = tanhf(s.x + bv.x); v0.y = tanhf(s.y + bv.y);
        v0.z = tanhf(s.z + bv.z); v0.w = tanhf(s.w + bv.w);
        *reinterpret_cast<float4*>(&n0s[row][4 * q]) = v0;
    }
    __syncthreads();

    // ---------- node 1: relu(n0@Wh[1] + b[1]) + n0 ----------
    {
        float4 a0 = {0.f, 0.f, 0.f, 0.f}, a1 = {0.f, 0.f, 0.f, 0.f};
        mv_partial(Wh + (size_t)H_ * H_, n0s[0], n0s[1], a0, a1, q, kc);
        part[kc][0][q] = a0;
        part[kc][1][q] = a1;
    }
    __syncthreads();

    if (tid < 128) {
        const int row = tid >> 6;
        float4 s = reduce8(part, row, q);
        float4 bv = *reinterpret_cast<const float4*>(bias + H_ + 4 * q);
        u.x = fmaxf(s.x + bv.x, 0.f) + v0.x;
        u.y = fmaxf(s.y + bv.y, 0.f) + v0.y;
        u.z = fmaxf(s.z + bv.z, 0.f) + v0.z;
        u.w = fmaxf(s.w + bv.w, 0.f) + v0.w;
        *reinterpret_cast<float4*>(&n1s[row][4 * q]) = u;
    }
    __syncthreads();

    // ---------- node 2: sigmoid(n1@Wh[2] + b[2]) + n0; h = 0.5*(n1+n2) ----------
    {
        float4 a0 = {0.f, 0.f, 0.f, 0.f}, a1 = {0.f, 0.f, 0.f, 0.f};
        mv_partial(Wh + 2 * (size_t)H_ * H_, n1s[0], n1s[1], a0, a1, q, kc);
        part[kc][0][q] = a0;
        part[kc][1][q] = a1;
    }
    __syncthreads();

    if (tid < 128) {
        const int row = tid >> 6;
        float4 s = reduce8(part, row, q);
        float4 bv = *reinterpret_cast<const float4*>(bias + 2 * H_ + 4 * q);
        float4 g;
        g.x = 1.f / (1.f + expf(-(s.x + bv.x))) + v0.x;
        g.y = 1.f / (1.f + expf(-(s.y + bv.y))) + v0.y;
        g.z = 1.f / (1.f + expf(-(s.z + bv.z))) + v0.z;
        g.w = 1.f / (1.f + expf(-(s.w + bv.w))) + v0.w;
        float4 hn = make_float4(0.5f * (u.x + g.x), 0.5f * (u.y + g.y),
                                0.5f * (u.z + g.z), 0.5f * (u.w + g.w));
        *reinterpret_cast<float4*>(&h[row][4 * q]) = hn;   // h last read 5 syncs ago
        float* op = (row == 0) ? o0 : o1;
        if (op) *reinterpret_cast<float4*>(op + 4 * q) = hn;
    }
    __syncthreads();
}

__global__ void __launch_bounds__(NT, 1)
rnn_persist_kernel(const float* __restrict__ x,       // [B,T,D]
                   const float* __restrict__ hidden,  // [L,B,H]
                   const float* __restrict__ Win0,    // [T,D,H]
                   const float* __restrict__ Wh0,     // [T,3,H,H]
                   const float* __restrict__ b0,      // [T,3,H]
                   const float* __restrict__ Win1,    // [T,H,H]
                   const float* __restrict__ Wh1,     // [T,3,H,H]
                   const float* __restrict__ b1,      // [T,3,H]
                   float* __restrict__ out,           // [B,T,H]
                   float* __restrict__ hout)          // [L,B,H]
{
    __shared__ __align__(16) float xs[2][H_];
    __shared__ __align__(16) float h0s[2][H_];
    __shared__ __align__(16) float h1s[2][H_];
    __shared__ __align__(16) float n0s[2][H_];
    __shared__ __align__(16) float n1s[2][H_];
    __shared__ __align__(16) float4 part[8][2][64];

    const int tid = threadIdx.x;
    const int q = tid & 63;
    const int kc = tid >> 6;
    const int r0 = blockIdx.x * 2;

    // load initial hidden state: hidden[l][r0+row][:]
    for (int i = tid; i < 2 * H_; i += NT) {
        int row = i >> 8, j = i & 255;
        h0s[row][j] = hidden[(r0 + row) * H_ + j];
        h1s[row][j] = hidden[(B_ + r0 + row) * H_ + j];
    }
    __syncthreads();

    for (int t = 0; t < T_; ++t) {
        // layer-0 inputs for this timestep
        {
            int row = tid >> 8, j = tid & 255;
            xs[row][j] = x[((size_t)(r0 + row) * T_ + t) * D_ + j];
        }
        __syncthreads();

        cell(xs, h0s, n0s, n1s, part,
             Win0 + (size_t)t * D_ * H_,
             Wh0 + (size_t)t * 3 * H_ * H_,
             b0 + (size_t)t * 3 * H_,
             tid, q, kc, nullptr, nullptr);

        cell(h0s, h1s, n0s, n1s, part,
             Win1 + (size_t)t * H_ * H_,
             Wh1 + (size_t)t * 3 * H_ * H_,
             b1 + (size_t)t * 3 * H_,
             tid, q, kc,
             out + ((size_t)r0 * T_ + t) * H_,
             out + ((size_t)(r0 + 1) * T_ + t) * H_);
    }

    // final hidden state
    for (int i = tid; i < 2 * H_; i += NT) {
        int row = i >> 8, j = i & 255;
        hout[(r0 + row) * H_ + j] = h0s[row][j];
        hout[(B_ + r0 + row) * H_ + j] = h1s[row][j];
    }
}

extern "C" void kernel_launch(void* const* d_in, const int* in_sizes, int n_in,
                              void* d_out, int out_size) {
    const float* x      = (const float*)d_in[0];
    const float* hidden = (const float*)d_in[1];
    const float* Win0   = (const float*)d_in[2];
    const float* Wh0    = (const float*)d_in[3];
    const float* b0     = (const float*)d_in[4];
    const float* Win1   = (const float*)d_in[5];
    const float* Wh1    = (const float*)d_in[6];
    const float* b1     = (const float*)d_in[7];

    float* out  = (float*)d_out;                        // [B,T,H]
    float* hout = out + (size_t)B_ * T_ * H_;           // [L,B,H]

    rnn_persist_kernel<<<B_ / 2, NT>>>(x, hidden, Win0, Wh0, b0,
                                       Win1, Wh1, b1, out, hout);
}

// round 5
// speedup vs baseline: 2.4133x; 1.0040x over previous
#include <cuda_runtime.h>
#include <cstdint>

#define B_ 128
#define T_ 64
#define D_ 256
#define H_ 256
#define NT 512
#define HALF_ 128

// 64 clusters of 2 CTAs (128 CTAs total, one wave on 148 SMs).
// Cluster c owns batch rows 2c, 2c+1. Rank r computes output columns
// [r*128, r*128+128) of every GEMM stage -> per-CTA weight traffic and FMA
// work halve vs the 64-CTA version. Activation halves are exchanged through
// DSMEM (st.shared::cluster) with a 2-deep mbarrier ring; no global sync.
// Thread (q = tid&31, kc = tid>>5): 4 output columns (rank*128 + 4q ..+3),
// k-chunk of 16. 64 reducer threads fold 16 partials, apply bias+activation,
// publish locally + to the peer CTA.

__device__ __forceinline__ void f4fma(float4& a, float s, const float4 w) {
    a.x = fmaf(s, w.x, a.x); a.y = fmaf(s, w.y, a.y);
    a.z = fmaf(s, w.z, a.z); a.w = fmaf(s, w.w, a.w);
}
__device__ __forceinline__ float4 f4add(float4 a, float4 b) {
    return make_float4(a.x + b.x, a.y + b.y, a.z + b.z, a.w + b.w);
}
__device__ __forceinline__ uint32_t smem_u32(const void* p) {
    return (uint32_t)__cvta_generic_to_shared(p);
}
__device__ __forceinline__ void mbar_init(uint32_t a, uint32_t n) {
    asm volatile("mbarrier.init.shared.b64 [%0], %1;" :: "r"(a), "r"(n) : "memory");
}
__device__ __forceinline__ void mbar_arrive_local(uint32_t a) {
    asm volatile("mbarrier.arrive.shared.b64 _, [%0];" :: "r"(a) : "memory");
}
__device__ __forceinline__ void mbar_arrive_peer(uint32_t a, uint32_t peer) {
    asm volatile("{\n\t.reg .b32 r;\n\t"
                 "mapa.shared::cluster.u32 r, %0, %1;\n\t"
                 "mbarrier.arrive.release.cluster.shared::cluster.b64 _, [r];\n\t}"
                 :: "r"(a), "r"(peer) : "memory");
}
__device__ __forceinline__ void mbar_wait(uint32_t a, uint32_t parity) {
    asm volatile("{\n\t.reg .pred P;\n\t"
                 "WL%=:\n\t"
                 "mbarrier.try_wait.parity.acquire.cluster.shared::cta.b64 P, [%0], %1, 0x989680;\n\t"
                 "@P bra WD%=;\n\t"
                 "bra WL%=;\n\t"
                 "WD%=:\n\t}"
                 :: "r"(a), "r"(parity) : "memory");
}
__device__ __forceinline__ void st_peer_f4(uint32_t a, uint32_t peer, float4 v) {
    asm volatile("{\n\t.reg .b32 r;\n\t"
                 "mapa.shared::cluster.u32 r, %0, %1;\n\t"
                 "st.shared::cluster.f32 [r],    %2;\n\t"
                 "st.shared::cluster.f32 [r+4],  %3;\n\t"
                 "st.shared::cluster.f32 [r+8],  %4;\n\t"
                 "st.shared::cluster.f32 [r+12], %5;\n\t}"
                 :: "r"(a), "r"(peer), "f"(v.x), "f"(v.y), "f"(v.z), "f"(v.w)
                 : "memory");
}
__device__ __forceinline__ void cluster_sync_() {
    asm volatile("barrier.cluster.arrive.aligned;" ::: "memory");
    asm volatile("barrier.cluster.wait.aligned;" ::: "memory");
}

// acc += act[rows][kc*16 .. +15] @ W[k, cols 4*colq .. +3]
__device__ __forceinline__ void mv_half(
    const float* __restrict__ W, const float (&act)[2][H_],
    float4& acc0, float4& acc1, int colq, int kc)
{
    const float4* __restrict__ w4 = reinterpret_cast<const float4*>(W)
        + (size_t)(kc * 16) * (H_ / 4) + colq;
    const float4* __restrict__ a0 = reinterpret_cast<const float4*>(act[0]) + kc * 4;
    const float4* __restrict__ a1 = reinterpret_cast<const float4*>(act[1]) + kc * 4;
    #pragma unroll
    for (int g = 0; g < 2; ++g) {
        float4 w[8];
        #pragma unroll
        for (int k = 0; k < 8; ++k) w[k] = w4[(size_t)(g * 8 + k) * (H_ / 4)];
        float4 A0a = a0[g * 2], A0b = a0[g * 2 + 1];
        float4 A1a = a1[g * 2], A1b = a1[g * 2 + 1];
        f4fma(acc0, A0a.x, w[0]); f4fma(acc1, A1a.x, w[0]);
        f4fma(acc0, A0a.y, w[1]); f4fma(acc1, A1a.y, w[1]);
        f4fma(acc0, A0a.z, w[2]); f4fma(acc1, A1a.z, w[2]);
        f4fma(acc0, A0a.w, w[3]); f4fma(acc1, A1a.w, w[3]);
        f4fma(acc0, A0b.x, w[4]); f4fma(acc1, A1b.x, w[4]);
        f4fma(acc0, A0b.y, w[5]); f4fma(acc1, A1b.y, w[5]);
        f4fma(acc0, A0b.z, w[6]); f4fma(acc1, A1b.z, w[6]);
        f4fma(acc0, A0b.w, w[7]); f4fma(acc1, A1b.w, w[7]);
    }
}

__device__ __forceinline__ float4 reduce16(const float4 (&p)[16][2][32], int row, int q) {
    float4 s0 = f4add(p[0][row][q],  p[1][row][q]);
    float4 s1 = f4add(p[2][row][q],  p[3][row][q]);
    float4 s2 = f4add(p[4][row][q],  p[5][row][q]);
    float4 s3 = f4add(p[6][row][q],  p[7][row][q]);
    float4 s4 = f4add(p[8][row][q],  p[9][row][q]);
    float4 s5 = f4add(p[10][row][q], p[11][row][q]);
    float4 s6 = f4add(p[12][row][q], p[13][row][q]);
    float4 s7 = f4add(p[14][row][q], p[15][row][q]);
    s0 = f4add(s0, s1); s2 = f4add(s2, s3);
    s4 = f4add(s4, s5); s6 = f4add(s6, s7);
    return f4add(f4add(s0, s2), f4add(s4, s6));
}

__device__ __forceinline__ void cell(
    const float (&in)[2][H_], float (&h)[2][H_],
    float (&n0s)[2][H_], float (&n1s)[2][H_],
    float4 (&part)[16][2][32],
    const float* __restrict__ Wi, const float* __restrict__ Wh,
    const float* __restrict__ bias,
    int tid, int q, int kc, int rank, uint32_t peer,
    uint32_t bar0, uint32_t bar1, uint32_t& ph,
    float* __restrict__ o0, float* __restrict__ o1)
{
    const int colq = rank * 32 + q;
    const int rrow = tid >> 5;        // reducer row (tid<64)
    const int rq = tid & 31;
    const int rcol = rank * HALF_ + 4 * rq;

    float4 v0 = {0.f, 0.f, 0.f, 0.f};
    float4 u  = {0.f, 0.f, 0.f, 0.f};

    // ---------- node 0: tanh(x@Wi + h@Wh[0] + b[0]) ----------
    {
        float4 a0 = {0.f,0.f,0.f,0.f}, a1 = {0.f,0.f,0.f,0.f};
        mv_half(Wi, in, a0, a1, colq, kc);
        mv_half(Wh, h, a0, a1, colq, kc);
        part[kc][0][q] = a0; part[kc][1][q] = a1;
    }
    __syncthreads();
    if (tid < 64) {
        float4 s = reduce16(part, rrow, rq);
        float4 bv = *reinterpret_cast<const float4*>(bias + rcol);
        v0.x = tanhf(s.x + bv.x); v0.y = tanhf(s.y + bv.y);
        v0.z = tanhf(s.z + bv.z); v0.w = tanhf(s.w + bv.w);
        *reinterpret_cast<float4*>(&n0s[rrow][rcol]) = v0;
        st_peer_f4(smem_u32(&n0s[rrow][rcol]), peer, v0);
        uint32_t b = (ph & 1) ? bar1 : bar0;
        mbar_arrive_local(b);
        mbar_arrive_peer(b, peer);
    }
    { uint32_t b = (ph & 1) ? bar1 : bar0; mbar_wait(b, (ph >> 1) & 1); ph++; }

    // ---------- node 1: relu(n0@Wh[1] + b[1]) + n0 ----------
    {
        float4 a0 = {0.f,0.f,0.f,0.f}, a1 = {0.f,0.f,0.f,0.f};
        mv_half(Wh + (size_t)H_ * H_, n0s, a0, a1, colq, kc);
        part[kc][0][q] = a0; part[kc][1][q] = a1;
    }
    __syncthreads();
    if (tid < 64) {
        float4 s = reduce16(part, rrow, rq);
        float4 bv = *reinterpret_cast<const float4*>(bias + H_ + rcol);
        u.x = fmaxf(s.x + bv.x, 0.f) + v0.x;
        u.y = fmaxf(s.y + bv.y, 0.f) + v0.y;
        u.z = fmaxf(s.z + bv.z, 0.f) + v0.z;
        u.w = fmaxf(s.w + bv.w, 0.f) + v0.w;
        *reinterpret_cast<float4*>(&n1s[rrow][rcol]) = u;
        st_peer_f4(smem_u32(&n1s[rrow][rcol]), peer, u);
        uint32_t b = (ph & 1) ? bar1 : bar0;
        mbar_arrive_local(b);
        mbar_arrive_peer(b, peer);
    }
    { uint32_t b = (ph & 1) ? bar1 : bar0; mbar_wait(b, (ph >> 1) & 1); ph++; }

    // ---------- node 2: sigmoid(n1@Wh[2] + b[2]) + n0; h = 0.5*(n1+n2) ----------
    {
        float4 a0 = {0.f,0.f,0.f,0.f}, a1 = {0.f,0.f,0.f,0.f};
        mv_half(Wh + 2 * (size_t)H_ * H_, n1s, a0, a1, colq, kc);
        part[kc][0][q] = a0; part[kc][1][q] = a1;
    }
    __syncthreads();
    if (tid < 64) {
        float4 s = reduce16(part, rrow, rq);
        float4 bv = *reinterpret_cast<const float4*>(bias + 2 * H_ + rcol);
        float4 g;
        g.x = 1.f / (1.f + expf(-(s.x + bv.x))) + v0.x;
        g.y = 1.f / (1.f + expf(-(s.y + bv.y))) + v0.y;
        g.z = 1.f / (1.f + expf(-(s.z + bv.z))) + v0.z;
        g.w = 1.f / (1.f + expf(-(s.w + bv.w))) + v0.w;
        float4 hn = make_float4(0.5f * (u.x + g.x), 0.5f * (u.y + g.y),
                                0.5f * (u.z + g.z), 0.5f * (u.w + g.w));
        *reinterpret_cast<float4*>(&h[rrow][rcol]) = hn;   // h last read at node 0
        st_peer_f4(smem_u32(&h[rrow][rcol]), peer, hn);
        if (o0) {
            float* op = rrow ? o1 : o0;
            *reinterpret_cast<float4*>(op + rcol) = hn;
        }
        uint32_t b = (ph & 1) ? bar1 : bar0;
        mbar_arrive_local(b);
        mbar_arrive_peer(b, peer);
    }
    { uint32_t b = (ph & 1) ? bar1 : bar0; mbar_wait(b, (ph >> 1) & 1); ph++; }
}

__global__ void __launch_bounds__(NT, 1) __cluster_dims__(2, 1, 1)
rnn_cluster_kernel(const float* __restrict__ x,       // [B,T,D]
                   const float* __restrict__ hidden,  // [L,B,H]
                   const float* __restrict__ Win0,    // [T,D,H]
                   const float* __restrict__ Wh0,     // [T,3,H,H]
                   const float* __restrict__ b0,      // [T,3,H]
                   const float* __restrict__ Win1,    // [T,H,H]
                   const float* __restrict__ Wh1,     // [T,3,H,H]
                   const float* __restrict__ b1,      // [T,3,H]
                   float* __restrict__ out,           // [B,T,H]
                   float* __restrict__ hout)          // [L,B,H]
{
    __shared__ __align__(16) float xs[2][H_];
    __shared__ __align__(16) float h0s[2][H_];
    __shared__ __align__(16) float h1s[2][H_];
    __shared__ __align__(16) float n0s[2][H_];
    __shared__ __align__(16) float n1s[2][H_];
    __shared__ __align__(16) float4 part[16][2][32];
    __shared__ __align__(8) unsigned long long mbar[2];

    const int tid = threadIdx.x;
    const int q = tid & 31;
    const int kc = tid >> 5;
    uint32_t rank;
    asm("mov.u32 %0, %%cluster_ctarank;" : "=r"(rank));
    const uint32_t peer = rank ^ 1u;
    const int r0 = (blockIdx.x >> 1) * 2;   // batch-row pair for this cluster

    const uint32_t bar0 = smem_u32(&mbar[0]);
    const uint32_t bar1 = smem_u32(&mbar[1]);
    if (tid == 0) { mbar_init(bar0, 128); mbar_init(bar1, 128); }
    __syncthreads();
    cluster_sync_();        // barriers visible cluster-wide before any remote op

    // initial hidden state (full vectors, each CTA loads everything)
    for (int i = tid; i < 2 * H_; i += NT) {
        int row = i >> 8, j = i & 255;
        h0s[row][j] = hidden[(r0 + row) * H_ + j];
        h1s[row][j] = hidden[(B_ + r0 + row) * H_ + j];
    }
    __syncthreads();

    uint32_t ph = 0;

    for (int t = 0; t < T_; ++t) {
        // layer-0 input rows for this timestep (full, loaded by both CTAs)
        {
            int row = tid >> 8, j = tid & 255;
            xs[row][j] = x[((size_t)(r0 + row) * T_ + t) * D_ + j];
        }
        __syncthreads();

        cell(xs, h0s, n0s, n1s, part,
             Win0 + (size_t)t * D_ * H_,
             Wh0 + (size_t)t * 3 * H_ * H_,
             b0 + (size_t)t * 3 * H_,
             tid, q, kc, (int)rank, peer, bar0, bar1, ph,
             nullptr, nullptr);

        cell(h0s, h1s, n0s, n1s, part,
             Win1 + (size_t)t * H_ * H_,
             Wh1 + (size_t)t * 3 * H_ * H_,
             b1 + (size_t)t * 3 * H_,
             tid, q, kc, (int)rank, peer, bar0, bar1, ph,
             out + ((size_t)r0 * T_ + t) * H_,
             out + ((size_t)(r0 + 1) * T_ + t) * H_);
    }

    // final hidden state: each CTA writes its half of the columns
    {
        int l = tid >> 8;
        int row = (tid >> 7) & 1;
        int j = (int)rank * HALF_ + (tid & 127);
        const float* src = l ? h1s[row] : h0s[row];
        hout[((size_t)l * B_ + r0 + row) * H_ + j] = src[j];
    }

    cluster_sync_();        // no CTA exits while its peer may still touch it
}

extern "C" void kernel_launch(void* const* d_in, const int* in_sizes, int n_in,
                              void* d_out, int out_size) {
    const float* x      = (const float*)d_in[0];
    const float* hidden = (const float*)d_in[1];
    const float* Win0   = (const float*)d_in[2];
    const float* Wh0    = (const float*)d_in[3];
    const float* b0     = (const float*)d_in[4];
    const float* Win1   = (const float*)d_in[5];
    const float* Wh1    = (const float*)d_in[6];
    const float* b1     = (const float*)d_in[7];

    float* out  = (float*)d_out;                        // [B,T,H]
    float* hout = out + (size_t)B_ * T_ * H_;           // [L,B,H]

    rnn_cluster_kernel<<<B_, NT>>>(x, hidden, Win0, Wh0, b0,
                                   Win1, Wh1, b1, out, hout);
}